// round 1
// baseline (speedup 1.0000x reference)
#include <cuda_runtime.h>
#include <cuda_bf16.h>
#include <math.h>

// Problem constants (fixed shapes for this problem instance)
#define NN   50000
#define TT   4
#define CC   128
#define FF   128
#define KK   3
#define EE   800000
#define MPAD 50048          // 391 * 128, padded row count for tile-aligned GEMM grids
#define LDA_TX 768          // row stride of TX buffer (6 blocks of 128)

// ---------------------------------------------------------------------------
// Device scratch (no allocations allowed)
// ---------------------------------------------------------------------------
__device__ __align__(16) float g_TX[(size_t)MPAD * 768];   // [Xp | Tx1x | Tx2x | H | Tx1h | Tx2h]
__device__ __align__(16) float g_Z [(size_t)MPAD * 512];   // gate pre-activations (i,f,c,o)
__device__ __align__(16) float g_Cst[(size_t)MPAD * 128];  // cell state
__device__ int   g_es[EE];
__device__ int   g_ed[EE];
__device__ int   g_deg[NN];
__device__ int   g_cnt[NN];
__device__ float g_dinv[NN];
__device__ int   g_rowptr[NN + 1];
__device__ int   g_cursor[NN];
__device__ int   g_col[EE];
__device__ float g_val[EE];
__device__ __align__(16) float g_Wall[768 * 512];
__device__ __align__(16) float g_bias[512];
__device__ __align__(16) float g_WpoolT[128 * 128];
__device__ int   g_flag64;

// ---------------------------------------------------------------------------
// Graph preprocessing
// ---------------------------------------------------------------------------
__global__ void k_detect(const void* edges) {
    // int32 data read as int64 pairs two random indices -> value >= 2^32 almost surely
    const long long* p = (const long long*)edges;
    int ok = 1;
    for (int i = 0; i < 512; ++i) {
        long long v = p[i];
        if (v < 0 || v >= NN) { ok = 0; break; }
    }
    g_flag64 = ok;
}

__global__ void k_convert(const void* edges) {
    int i = blockIdx.x * blockDim.x + threadIdx.x;
    if (i >= 2 * EE) return;
    int v;
    if (g_flag64) v = (int)((const long long*)edges)[i];
    else          v = ((const int*)edges)[i];
    if (i < EE) g_es[i] = v;
    else        g_ed[i - EE] = v;
}

__global__ void k_zero_counts() {
    int i = blockIdx.x * blockDim.x + threadIdx.x;
    if (i < NN)            g_deg[i] = 0;
    else if (i < 2 * NN)   g_cnt[i - NN] = 0;
}

__global__ void k_count() {
    int i = blockIdx.x * blockDim.x + threadIdx.x;
    if (i >= EE) return;
    atomicAdd(&g_deg[g_es[i]], 1);
    atomicAdd(&g_cnt[g_ed[i]], 1);
}

__global__ void k_dinv() {
    int i = blockIdx.x * blockDim.x + threadIdx.x;
    if (i >= NN) return;
    int d = g_deg[i];
    g_dinv[i] = (d > 0) ? rsqrtf((float)d) : 0.0f;
}

__global__ void k_scan() {   // single block, 1024 threads: exclusive scan of g_cnt
    __shared__ int sh[1024];
    const int t = threadIdx.x;
    const int CH = (NN + 1023) / 1024;   // 49
    int s = 0;
    int base0 = t * CH;
    for (int j = 0; j < CH; ++j) {
        int idx = base0 + j;
        if (idx < NN) s += g_cnt[idx];
    }
    sh[t] = s;
    __syncthreads();
    for (int off = 1; off < 1024; off <<= 1) {
        int v = (t >= off) ? sh[t - off] : 0;
        __syncthreads();
        sh[t] += v;
        __syncthreads();
    }
    int run = (t == 0) ? 0 : sh[t - 1];
    for (int j = 0; j < CH; ++j) {
        int idx = base0 + j;
        if (idx < NN) {
            g_rowptr[idx] = run;
            g_cursor[idx] = run;
            run += g_cnt[idx];
        }
    }
    if (t == 1023) g_rowptr[NN] = EE;
}

__global__ void k_fill() {
    int i = blockIdx.x * blockDim.x + threadIdx.x;
    if (i >= EE) return;
    int s = g_es[i], d = g_ed[i];
    int pos = atomicAdd(&g_cursor[d], 1);
    g_col[pos] = s;
    g_val[pos] = -(g_dinv[s] * g_dinv[d]);
}

// ---------------------------------------------------------------------------
// Weight / bias preparation
//   W_all[r, cc]: r = kblk*128 + rin (kblk: 0..2 = x-path T0..T2, 3..5 = h-path T0..T2)
//                 cc = gate*128 + c  (gate: 0=i,1=f,2=c,3=o)
//   conv_W layout [8, K, C, C], gate order (x_i,h_i,x_f,h_f,x_c,h_c,x_o,h_o)
// ---------------------------------------------------------------------------
__global__ void k_prep(const float* __restrict__ convW, const float* __restrict__ convb,
                       const float* __restrict__ gateb, const float* __restrict__ Wpool) {
    int i = blockIdx.x * blockDim.x + threadIdx.x;
    if (i < 768 * 512) {
        int r = i / 512, cc = i % 512;
        int kblk = r / 128, rin = r % 128;
        int gate = cc / 128, c = cc % 128;
        int k   = (kblk < 3) ? kblk : (kblk - 3);
        int idx = (kblk < 3) ? (2 * gate) : (2 * gate + 1);
        g_Wall[i] = convW[((size_t)(idx * KK + k)) * CC * CC + rin * CC + c];
    }
    if (i < 512) {
        int gate = i / 128, c = i % 128;
        g_bias[i] = convb[(2 * gate) * CC + c] + convb[(2 * gate + 1) * CC + c]
                  + gateb[gate * CC + c];
    }
    if (i < 128 * 128) {
        int f = i / 128, c = i % 128;
        g_WpoolT[i] = Wpool[c * FF + f];   // B[f][c] = W_pool[c][f]
    }
}

__global__ void k_zero_f4(float4* p, long n4) {
    long i = (long)blockIdx.x * blockDim.x + threadIdx.x;
    long stride = (long)gridDim.x * blockDim.x;
    float4 z = make_float4(0.f, 0.f, 0.f, 0.f);
    for (; i < n4; i += stride) p[i] = z;
}

// ---------------------------------------------------------------------------
// SGEMM: C[M, Ncols] = A[M, K] * B[K, Ncols]   (fp32, 128x128 tile, 8x8 micro)
// K and Ncols assumed multiples of 8 / 128; M guarded.
// ---------------------------------------------------------------------------
__global__ void __launch_bounds__(256) k_sgemm(
    const float* __restrict__ A, int lda,
    const float* __restrict__ B, int ldb,
    float* __restrict__ Cm, int ldc,
    int M, int Kd)
{
    __shared__ float As[8][128];
    __shared__ float Bs[8][128];

    const int tid = threadIdx.x;
    const int rowTile = blockIdx.y * 128;
    const int colTile = blockIdx.x * 128;

    const int arow = tid >> 1;
    const int acol = (tid & 1) * 4;
    const int brow = tid >> 5;
    const int bcol = (tid & 31) * 4;

    const int tx = (tid & 15) * 8;
    const int ty = (tid >> 4) * 8;

    float acc[8][8];
#pragma unroll
    for (int i = 0; i < 8; ++i)
#pragma unroll
        for (int j = 0; j < 8; ++j) acc[i][j] = 0.f;

    for (int k0 = 0; k0 < Kd; k0 += 8) {
        int gr = rowTile + arow;
        float4 av;
        if (gr < M) av = *(const float4*)&A[(long)gr * lda + k0 + acol];
        else        av = make_float4(0.f, 0.f, 0.f, 0.f);
        As[acol + 0][arow] = av.x;
        As[acol + 1][arow] = av.y;
        As[acol + 2][arow] = av.z;
        As[acol + 3][arow] = av.w;

        float4 bv = *(const float4*)&B[(long)(k0 + brow) * ldb + colTile + bcol];
        *(float4*)&Bs[brow][bcol] = bv;
        __syncthreads();

#pragma unroll
        for (int kk = 0; kk < 8; ++kk) {
            float ra[8], rb[8];
            *(float4*)&ra[0] = *(const float4*)&As[kk][ty];
            *(float4*)&ra[4] = *(const float4*)&As[kk][ty + 4];
            *(float4*)&rb[0] = *(const float4*)&Bs[kk][tx];
            *(float4*)&rb[4] = *(const float4*)&Bs[kk][tx + 4];
#pragma unroll
            for (int i = 0; i < 8; ++i)
#pragma unroll
                for (int j = 0; j < 8; ++j)
                    acc[i][j] += ra[i] * rb[j];
        }
        __syncthreads();
    }

#pragma unroll
    for (int i = 0; i < 8; ++i) {
        int gr = rowTile + ty + i;
        if (gr < M) {
            float4 v0 = make_float4(acc[i][0], acc[i][1], acc[i][2], acc[i][3]);
            float4 v1 = make_float4(acc[i][4], acc[i][5], acc[i][6], acc[i][7]);
            *(float4*)&Cm[(long)gr * ldc + colTile + tx]     = v0;
            *(float4*)&Cm[(long)gr * ldc + colTile + tx + 4] = v1;
        }
    }
}

// ---------------------------------------------------------------------------
// prop: out[n, :] = scale * sum_{e in row n} val[e] * xin[col[e], :]  (- sub[n,:])
// One warp per node, lane owns a float4 (32*4 = 128 channels). Row stride 768.
// ---------------------------------------------------------------------------
__global__ void k_prop(const float* __restrict__ xin, float* __restrict__ xout,
                       float scale, const float* __restrict__ sub)
{
    int gwarp = (blockIdx.x * blockDim.x + threadIdx.x) >> 5;
    int lane  = threadIdx.x & 31;
    if (gwarp >= NN) return;

    int start = g_rowptr[gwarp];
    int end   = g_rowptr[gwarp + 1];

    float4 acc = make_float4(0.f, 0.f, 0.f, 0.f);
    for (int e = start; e < end; ++e) {
        int   s = g_col[e];
        float w = g_val[e];
        float4 v = ((const float4*)&xin[(long)s * LDA_TX])[lane];
        acc.x += w * v.x; acc.y += w * v.y; acc.z += w * v.z; acc.w += w * v.w;
    }
    float4 o;
    if (sub) {
        float4 sv = ((const float4*)&sub[(long)gwarp * LDA_TX])[lane];
        o = make_float4(scale * acc.x - sv.x, scale * acc.y - sv.y,
                        scale * acc.z - sv.z, scale * acc.w - sv.w);
    } else {
        o = make_float4(scale * acc.x, scale * acc.y, scale * acc.z, scale * acc.w);
    }
    ((float4*)&xout[(long)gwarp * LDA_TX])[lane] = o;
}

// ---------------------------------------------------------------------------
// Gate fusion: LSTM cell update with peephole, writes H back into TX block 3
// ---------------------------------------------------------------------------
__device__ __forceinline__ float sigmoidf(float x) { return 1.f / (1.f + expf(-x)); }

__global__ void k_gate(const float* __restrict__ pw, float* __restrict__ out, int t) {
    int i = blockIdx.x * blockDim.x + threadIdx.x;
    if (i >= NN * 128) return;
    int n = i >> 7, c = i & 127;

    const float* z = &g_Z[(long)n * 512];
    float zi = z[c], zf = z[128 + c], zc = z[256 + c], zo = z[384 + c];
    float cold = g_Cst[(long)n * 128 + c];

    float w_ci = pw[c], w_cf = pw[128 + c], w_co = pw[256 + c];

    float I  = sigmoidf(zi + g_bias[c]       + w_ci * cold);
    float F  = sigmoidf(zf + g_bias[128 + c] + w_cf * cold);
    float Tc = tanhf  (zc + g_bias[256 + c]);
    float cnew = F * cold + I * Tc;
    float O  = sigmoidf(zo + g_bias[384 + c] + w_co * cnew);
    float h  = O * tanhf(cnew);

    g_Cst[(long)n * 128 + c] = cnew;
    g_TX[(long)n * LDA_TX + 384 + c] = h;                  // H block for next step
    out[((long)n * TT + t) * CC + c] = h;
}

// ---------------------------------------------------------------------------
// Host launcher (graph-capturable; default stream; no allocations)
// ---------------------------------------------------------------------------
extern "C" void kernel_launch(void* const* d_in, const int* in_sizes, int n_in,
                              void* d_out, int out_size)
{
    const float* X     = (const float*)d_in[0];   // [T, N, F_IN]
    const void*  edges = d_in[1];                 // [2, E] int64 or int32
    const float* Wpool = (const float*)d_in[2];   // [C, F_IN]
    const float* convW = (const float*)d_in[3];   // [8, K, C, C]
    const float* convb = (const float*)d_in[4];   // [8, C]
    const float* pw    = (const float*)d_in[5];   // [3, C]
    const float* gb    = (const float*)d_in[6];   // [4, C]
    float* out = (float*)d_out;                   // [N, T, C]

    float *TX, *Z, *Wall, *WpoolT, *Cst;
    cudaGetSymbolAddress((void**)&TX,     g_TX);
    cudaGetSymbolAddress((void**)&Z,      g_Z);
    cudaGetSymbolAddress((void**)&Wall,   g_Wall);
    cudaGetSymbolAddress((void**)&WpoolT, g_WpoolT);
    cudaGetSymbolAddress((void**)&Cst,    g_Cst);

    // --- graph preprocessing (per call; edges identical each call) ---
    k_detect<<<1, 1>>>(edges);
    k_convert<<<(2 * EE + 255) / 256, 256>>>(edges);
    k_zero_counts<<<(2 * NN + 255) / 256, 256>>>();
    k_count<<<(EE + 255) / 256, 256>>>();
    k_dinv<<<(NN + 255) / 256, 256>>>();
    k_scan<<<1, 1024>>>();
    k_fill<<<(EE + 255) / 256, 256>>>();
    k_prep<<<(768 * 512 + 255) / 256, 256>>>(convW, convb, gb, Wpool);

    // --- zero state buffers ---
    k_zero_f4<<<2048, 256>>>((float4*)TX,  (long)MPAD * 768 / 4);
    k_zero_f4<<<512,  256>>>((float4*)Cst, (long)MPAD * 128 / 4);

    const dim3 gemmPoolGrid(1, (MPAD / 128));    // 128-col output
    const dim3 gemmBigGrid (4, (MPAD / 128));    // 512-col output
    const int  propBlocks = (NN + 3) / 4;        // 4 warps/block, warp per node

    for (int t = 0; t < TT; ++t) {
        // Xp = X_t @ W_pool^T  -> TX block 0
        k_sgemm<<<gemmPoolGrid, 256>>>(X + (long)t * NN * FF, FF,
                                       WpoolT, 128, TX, LDA_TX, NN, FF);
        // Chebyshev basis of Xp
        k_prop<<<propBlocks, 128>>>(TX,        TX + 128, 1.f, nullptr);
        k_prop<<<propBlocks, 128>>>(TX + 128,  TX + 256, 2.f, TX);
        // Chebyshev basis of H (skip at t=0: H==0, blocks already zeroed)
        if (t > 0) {
            k_prop<<<propBlocks, 128>>>(TX + 384, TX + 512, 1.f, nullptr);
            k_prop<<<propBlocks, 128>>>(TX + 512, TX + 640, 2.f, TX + 384);
        }
        // Z = TX(N x 768) @ W_all(768 x 512)
        k_sgemm<<<gemmBigGrid, 256>>>(TX, LDA_TX, Wall, 512, Z, 512, NN, 768);
        // Gates + state update + output write
        k_gate<<<(NN * 128 + 255) / 256, 256>>>(pw, out, t);
    }
}

// round 4
// speedup vs baseline: 2.2114x; 2.2114x over previous
#include <cuda_runtime.h>
#include <cuda_bf16.h>
#include <math.h>
#include <stdint.h>

// Problem constants
#define NN   50000
#define TT   4
#define CC   128
#define FF   128
#define KK   3
#define EE   800000
#define MPAD 50048          // 391 * 128
#define LDTX 768

#define SWZ(b) ((b) ^ (((b) >> 3) & 0x70))

// ---------------------------------------------------------------------------
// Device scratch
// ---------------------------------------------------------------------------
__device__ __align__(16) float g_TX [(size_t)MPAD * 768];   // fp32: [Xp|Tx1x|Tx2x|H|Tx1h|Tx2h]
__device__ __align__(16) __nv_bfloat16 g_TXh[(size_t)MPAD * 768];
__device__ __align__(16) __nv_bfloat16 g_TXl[(size_t)MPAD * 768];
__device__ __align__(16) float g_Z  [(size_t)MPAD * 512];
__device__ __align__(16) float g_Cst[(size_t)MPAD * 128];
__device__ __align__(16) __nv_bfloat16 g_Xh[(size_t)TT * MPAD * 128];
__device__ __align__(16) __nv_bfloat16 g_Xl[(size_t)TT * MPAD * 128];
__device__ __align__(16) __nv_bfloat16 g_WTh[512 * 768];    // B main GEMM, [n][k]
__device__ __align__(16) __nv_bfloat16 g_WTl[512 * 768];
__device__ __align__(16) __nv_bfloat16 g_Wph[128 * 128];    // B pool GEMM, [c][f]
__device__ __align__(16) __nv_bfloat16 g_Wpl[128 * 128];
__device__ __align__(16) float g_bias[512];
__device__ int   g_es[EE];
__device__ int   g_ed[EE];
__device__ int   g_deg[NN];
__device__ int   g_cnt[NN];
__device__ float g_dinv[NN];
__device__ int   g_rowptr[NN + 1];
__device__ int   g_cursor[NN];
__device__ int   g_col[EE];
__device__ float g_val[EE];
__device__ int   g_flag64;

__device__ __forceinline__ void split_bf16(float x, __nv_bfloat16& h, __nv_bfloat16& l) {
    h = __float2bfloat16(x);
    l = __float2bfloat16(x - __bfloat162float(h));
}

__device__ __forceinline__ uint32_t smem_u32(const void* p) {
    uint32_t a;
    asm("{ .reg .u64 t; cvta.to.shared.u64 t, %1; cvt.u32.u64 %0, t; }" : "=r"(a) : "l"(p));
    return a;
}

// ---------------------------------------------------------------------------
// Graph preprocessing
// ---------------------------------------------------------------------------
__global__ void k_detect(const void* edges) {
    const long long* p = (const long long*)edges;
    int ok = 1;
    for (int i = 0; i < 512; ++i) {
        long long v = p[i];
        if (v < 0 || v >= NN) { ok = 0; break; }
    }
    g_flag64 = ok;
}
__global__ void k_convert(const void* edges) {
    int i = blockIdx.x * blockDim.x + threadIdx.x;
    if (i >= 2 * EE) return;
    int v;
    if (g_flag64) v = (int)((const long long*)edges)[i];
    else          v = ((const int*)edges)[i];
    if (i < EE) g_es[i] = v;
    else        g_ed[i - EE] = v;
}
__global__ void k_zero_counts() {
    int i = blockIdx.x * blockDim.x + threadIdx.x;
    if (i < NN)          g_deg[i] = 0;
    else if (i < 2 * NN) g_cnt[i - NN] = 0;
}
__global__ void k_count() {
    int i = blockIdx.x * blockDim.x + threadIdx.x;
    if (i >= EE) return;
    atomicAdd(&g_deg[g_es[i]], 1);
    atomicAdd(&g_cnt[g_ed[i]], 1);
}
__global__ void k_dinv() {
    int i = blockIdx.x * blockDim.x + threadIdx.x;
    if (i >= NN) return;
    int d = g_deg[i];
    g_dinv[i] = (d > 0) ? rsqrtf((float)d) : 0.0f;
}
__global__ void k_scan() {
    __shared__ int sh[1024];
    const int t = threadIdx.x;
    const int CH = (NN + 1023) / 1024;
    int s = 0;
    int base0 = t * CH;
    for (int j = 0; j < CH; ++j) { int idx = base0 + j; if (idx < NN) s += g_cnt[idx]; }
    sh[t] = s;
    __syncthreads();
    for (int off = 1; off < 1024; off <<= 1) {
        int v = (t >= off) ? sh[t - off] : 0;
        __syncthreads();
        sh[t] += v;
        __syncthreads();
    }
    int run = (t == 0) ? 0 : sh[t - 1];
    for (int j = 0; j < CH; ++j) {
        int idx = base0 + j;
        if (idx < NN) { g_rowptr[idx] = run; g_cursor[idx] = run; run += g_cnt[idx]; }
    }
    if (t == 1023) g_rowptr[NN] = EE;
}
__global__ void k_fill() {
    int i = blockIdx.x * blockDim.x + threadIdx.x;
    if (i >= EE) return;
    int s = g_es[i], d = g_ed[i];
    int pos = atomicAdd(&g_cursor[d], 1);
    g_col[pos] = s;
    g_val[pos] = -(g_dinv[s] * g_dinv[d]);
}

// ---------------------------------------------------------------------------
// Weight prep
// ---------------------------------------------------------------------------
__global__ void k_prep(const float* __restrict__ convW, const float* __restrict__ convb,
                       const float* __restrict__ gateb, const float* __restrict__ Wpool) {
    int i = blockIdx.x * blockDim.x + threadIdx.x;
    if (i < 512 * 768) {
        int cc = i / 768, r = i % 768;
        int kblk = r >> 7, rin = r & 127;
        int gate = cc >> 7, ch = cc & 127;
        int k   = kblk % 3;
        int idx = (kblk < 3) ? (2 * gate) : (2 * gate + 1);
        float v = convW[((size_t)(idx * KK + k)) * CC * CC + rin * CC + ch];
        __nv_bfloat16 h, l; split_bf16(v, h, l);
        g_WTh[i] = h; g_WTl[i] = l;
    }
    if (i < 512) {
        int gate = i / 128, c = i % 128;
        g_bias[i] = convb[(2 * gate) * CC + c] + convb[(2 * gate + 1) * CC + c] + gateb[gate * CC + c];
    }
    if (i < 128 * 128) {
        __nv_bfloat16 h, l; split_bf16(Wpool[i], h, l);
        g_Wph[i] = h; g_Wpl[i] = l;
    }
}

__global__ void k_splitX(const float* __restrict__ X) {
    int i = blockIdx.x * blockDim.x + threadIdx.x;
    if (i >= TT * NN * 128) return;
    int t = i / (NN * 128);
    int r = i - t * (NN * 128);
    int n = r >> 7, f = r & 127;
    __nv_bfloat16 h, l; split_bf16(X[i], h, l);
    size_t o = ((size_t)t * MPAD + n) * 128 + f;
    g_Xh[o] = h; g_Xl[o] = l;
}

__global__ void k_zero_f4(float4* p, long n4) {
    long i = (long)blockIdx.x * blockDim.x + threadIdx.x;
    long stride = (long)gridDim.x * blockDim.x;
    float4 z = make_float4(0.f, 0.f, 0.f, 0.f);
    for (; i < n4; i += stride) p[i] = z;
}

// ---------------------------------------------------------------------------
// mma.sync bf16-split GEMM (base ISA)
// out[M, Ncols] = (Ah+Al)[M,K] @ (Bh+Bl)^T, B stored [Ncols][K] row-major.
// D = Ah*Bh + Ah*Bl + Al*Bh (fp32 register accumulators).
// CTA tile 128x128, warp tile 64x32 (8 warps), K chunk 64, cp.async 2-stage.
// ---------------------------------------------------------------------------
__device__ __forceinline__ void ldsm4(uint32_t addr, uint32_t* r) {
    asm volatile("ldmatrix.sync.aligned.m8n8.x4.shared.b16 {%0,%1,%2,%3}, [%4];"
        : "=r"(r[0]), "=r"(r[1]), "=r"(r[2]), "=r"(r[3]) : "r"(addr));
}
__device__ __forceinline__ void mma16816(float* d, const uint32_t* a, const uint32_t* b) {
    asm volatile("mma.sync.aligned.m16n8k16.row.col.f32.bf16.bf16.f32 "
        "{%0,%1,%2,%3}, {%4,%5,%6,%7}, {%8,%9}, {%0,%1,%2,%3};"
        : "+f"(d[0]), "+f"(d[1]), "+f"(d[2]), "+f"(d[3])
        : "r"(a[0]), "r"(a[1]), "r"(a[2]), "r"(a[3]), "r"(b[0]), "r"(b[1]));
}
__device__ __forceinline__ void cp16(uint32_t dst, const void* src) {
    asm volatile("cp.async.cg.shared.global [%0], [%1], 16;" :: "r"(dst), "l"(src));
}

#define GBUF 65536u   // per stage: Ah 16K | Al 16K | Bh 16K | Bl 16K

__global__ void __launch_bounds__(256) k_mgemm(
    const __nv_bfloat16* __restrict__ Ah, const __nv_bfloat16* __restrict__ Al, int lda,
    const __nv_bfloat16* __restrict__ Bh, const __nv_bfloat16* __restrict__ Bl, int ldb,
    int K,
    float* __restrict__ outF, int ldc,
    __nv_bfloat16* __restrict__ oBh, __nv_bfloat16* __restrict__ oBl)
{
    extern __shared__ char sm[];
    const int tid  = threadIdx.x;
    const int wid  = tid >> 5;
    const int lane = tid & 31;
    const int rowTile = blockIdx.y * 128;
    const int colTile = blockIdx.x * 128;
    const int warp_m = (wid >> 2) * 64;
    const int warp_n = (wid & 3) * 32;
    const uint32_t smb = smem_u32(sm);
    const int nch = K >> 6;

    float d[4][4][4];
#pragma unroll
    for (int a = 0; a < 4; ++a)
#pragma unroll
        for (int b = 0; b < 4; ++b)
#pragma unroll
            for (int q = 0; q < 4; ++q) d[a][b][q] = 0.f;

    auto issue = [&](int c) {
        const uint32_t dstBase = smb + (uint32_t)(c & 1) * GBUF;
#pragma unroll
        for (int it = 0; it < 16; ++it) {
            int i  = tid + it * 256;
            int sp = i >> 10;                 // 0 Ah,1 Al,2 Bh,3 Bl
            int r  = (i & 1023) >> 3;
            int f  = i & 7;
            const __nv_bfloat16* base = (sp == 0) ? Ah : (sp == 1) ? Al : (sp == 2) ? Bh : Bl;
            int rb = (sp < 2) ? rowTile : colTile;
            int ld = (sp < 2) ? lda : ldb;
            const void* src = base + (size_t)(rb + r) * ld + c * 64 + f * 8;
            cp16(dstBase + sp * 16384u + SWZ((uint32_t)(r * 128 + f * 16)), src);
        }
        asm volatile("cp.async.commit_group;" ::: "memory");
    };

    issue(0);
    if (nch > 1) issue(1);

    for (int c = 0; c < nch; ++c) {
        if (c < nch - 1) asm volatile("cp.async.wait_group 1;" ::: "memory");
        else             asm volatile("cp.async.wait_group 0;" ::: "memory");
        __syncthreads();

        const uint32_t sm0 = smb + (uint32_t)(c & 1) * GBUF;
        const int laneRowA = warp_m + (lane & 15);
        const uint32_t kbA = (uint32_t)((lane >> 4) * 16);
        const int nrowB = warp_n + (lane & 7) + ((lane >> 4) << 3);
        const uint32_t kbB = (uint32_t)(((lane >> 3) & 1) * 16);

#pragma unroll
        for (int ks = 0; ks < 4; ++ks) {
            uint32_t ah[4][4], al[4][4], bh[4][2], bl[4][2];
#pragma unroll
            for (int mt = 0; mt < 4; ++mt) {
                uint32_t off = SWZ((uint32_t)((laneRowA + mt * 16) * 128) + ks * 32 + kbA);
                ldsm4(sm0 + off, ah[mt]);
                ldsm4(sm0 + 16384u + off, al[mt]);
            }
#pragma unroll
            for (int np = 0; np < 2; ++np) {
                uint32_t off = SWZ((uint32_t)((nrowB + np * 16) * 128) + ks * 32 + kbB);
                uint32_t r0[4], r1[4];
                ldsm4(sm0 + 32768u + off, r0);
                ldsm4(sm0 + 49152u + off, r1);
                bh[2 * np][0] = r0[0]; bh[2 * np][1] = r0[1];
                bh[2 * np + 1][0] = r0[2]; bh[2 * np + 1][1] = r0[3];
                bl[2 * np][0] = r1[0]; bl[2 * np][1] = r1[1];
                bl[2 * np + 1][0] = r1[2]; bl[2 * np + 1][1] = r1[3];
            }
#pragma unroll
            for (int mt = 0; mt < 4; ++mt)
#pragma unroll
                for (int nt = 0; nt < 4; ++nt) {
                    mma16816(d[mt][nt], ah[mt], bh[nt]);
                    mma16816(d[mt][nt], ah[mt], bl[nt]);
                    mma16816(d[mt][nt], al[mt], bh[nt]);
                }
        }
        if (c + 2 < nch) {
            __syncthreads();
            issue(c + 2);
        }
    }

    // --- epilogue ---
#pragma unroll
    for (int mt = 0; mt < 4; ++mt) {
        int m0 = rowTile + warp_m + mt * 16 + (lane >> 2);
#pragma unroll
        for (int nt = 0; nt < 4; ++nt) {
            int n0 = colTile + warp_n + nt * 8 + (lane & 3) * 2;
#pragma unroll
            for (int half = 0; half < 2; ++half) {
                int m = m0 + half * 8;
                float v0 = d[mt][nt][half * 2], v1 = d[mt][nt][half * 2 + 1];
                *(float2*)&outF[(size_t)m * ldc + n0] = make_float2(v0, v1);
                if (oBh) {
                    __nv_bfloat16 h0, l0, h1, l1;
                    split_bf16(v0, h0, l0); split_bf16(v1, h1, l1);
                    size_t bo = (size_t)m * 768 + n0;
                    *(__nv_bfloat162*)&oBh[bo] = __halves2bfloat162(h0, h1);
                    *(__nv_bfloat162*)&oBl[bo] = __halves2bfloat162(l0, l1);
                }
            }
        }
    }
}

// ---------------------------------------------------------------------------
// Fused dual-block Chebyshev propagation
// ---------------------------------------------------------------------------
__device__ __forceinline__ void prop_write(size_t n, int off, int lane, float4 o) {
    *(float4*)&g_TX[n * LDTX + off + lane * 4] = o;
    __nv_bfloat16 h0, l0, h1, l1, h2, l2, h3, l3;
    split_bf16(o.x, h0, l0); split_bf16(o.y, h1, l1);
    split_bf16(o.z, h2, l2); split_bf16(o.w, h3, l3);
    size_t bo = n * LDTX + off + lane * 4;
    *(__nv_bfloat162*)&g_TXh[bo]     = __halves2bfloat162(h0, h1);
    *(__nv_bfloat162*)&g_TXh[bo + 2] = __halves2bfloat162(h2, h3);
    *(__nv_bfloat162*)&g_TXl[bo]     = __halves2bfloat162(l0, l1);
    *(__nv_bfloat162*)&g_TXl[bo + 2] = __halves2bfloat162(l2, l3);
}

__global__ void k_prop2(int in_x, int out_x, int sub_x,
                        int in_h, int out_h, int sub_h,
                        float sc, int do_h)
{
    int gwarp = (blockIdx.x * blockDim.x + threadIdx.x) >> 5;
    int lane  = threadIdx.x & 31;
    if (gwarp >= NN) return;

    int start = g_rowptr[gwarp];
    int end   = g_rowptr[gwarp + 1];

    float4 ax = make_float4(0.f, 0.f, 0.f, 0.f);
    float4 ahh = make_float4(0.f, 0.f, 0.f, 0.f);
    for (int e = start; e < end; ++e) {
        int   s = g_col[e];
        float w = g_val[e];
        const float* rp = &g_TX[(size_t)s * LDTX];
        float4 vx = *(const float4*)(rp + in_x + lane * 4);
        ax.x += w * vx.x; ax.y += w * vx.y; ax.z += w * vx.z; ax.w += w * vx.w;
        if (do_h) {
            float4 vh = *(const float4*)(rp + in_h + lane * 4);
            ahh.x += w * vh.x; ahh.y += w * vh.y; ahh.z += w * vh.z; ahh.w += w * vh.w;
        }
    }
    {
        float4 o = make_float4(sc * ax.x, sc * ax.y, sc * ax.z, sc * ax.w);
        if (sub_x >= 0) {
            float4 sv = *(const float4*)&g_TX[(size_t)gwarp * LDTX + sub_x + lane * 4];
            o.x -= sv.x; o.y -= sv.y; o.z -= sv.z; o.w -= sv.w;
        }
        prop_write(gwarp, out_x, lane, o);
    }
    if (do_h) {
        float4 o = make_float4(sc * ahh.x, sc * ahh.y, sc * ahh.z, sc * ahh.w);
        if (sub_h >= 0) {
            float4 sv = *(const float4*)&g_TX[(size_t)gwarp * LDTX + sub_h + lane * 4];
            o.x -= sv.x; o.y -= sv.y; o.z -= sv.z; o.w -= sv.w;
        }
        prop_write(gwarp, out_h, lane, o);
    }
}

// ---------------------------------------------------------------------------
// Gate fusion
// ---------------------------------------------------------------------------
__device__ __forceinline__ float sigmoidf(float x) { return 1.f / (1.f + expf(-x)); }

__global__ void k_gate(const float* __restrict__ pw, float* __restrict__ out, int t) {
    int i = blockIdx.x * blockDim.x + threadIdx.x;
    if (i >= NN * 128) return;
    int n = i >> 7, c = i & 127;

    const float* z = &g_Z[(size_t)n * 512];
    float zi = z[c], zf = z[128 + c], zc = z[256 + c], zo = z[384 + c];
    float cold = g_Cst[(size_t)n * 128 + c];

    float I  = sigmoidf(zi + g_bias[c]       + pw[c]       * cold);
    float F  = sigmoidf(zf + g_bias[128 + c] + pw[128 + c] * cold);
    float Tc = tanhf  (zc + g_bias[256 + c]);
    float cnew = F * cold + I * Tc;
    float O  = sigmoidf(zo + g_bias[384 + c] + pw[256 + c] * cnew);
    float h  = O * tanhf(cnew);

    g_Cst[(size_t)n * 128 + c] = cnew;
    g_TX[(size_t)n * LDTX + 384 + c] = h;
    __nv_bfloat16 hh, hl; split_bf16(h, hh, hl);
    g_TXh[(size_t)n * LDTX + 384 + c] = hh;
    g_TXl[(size_t)n * LDTX + 384 + c] = hl;
    out[((size_t)n * TT + t) * CC + c] = h;
}

// ---------------------------------------------------------------------------
// Host launcher
// ---------------------------------------------------------------------------
extern "C" void kernel_launch(void* const* d_in, const int* in_sizes, int n_in,
                              void* d_out, int out_size)
{
    const float* X     = (const float*)d_in[0];
    const void*  edges = d_in[1];
    const float* Wpool = (const float*)d_in[2];
    const float* convW = (const float*)d_in[3];
    const float* convb = (const float*)d_in[4];
    const float* pw    = (const float*)d_in[5];
    const float* gb    = (const float*)d_in[6];
    float* out = (float*)d_out;

    float *TX, *Z, *Cst;
    __nv_bfloat16 *TXh, *TXl, *Xh, *Xl, *WTh, *WTl, *Wph, *Wpl;
    cudaGetSymbolAddress((void**)&TX,  g_TX);
    cudaGetSymbolAddress((void**)&Z,   g_Z);
    cudaGetSymbolAddress((void**)&Cst, g_Cst);
    cudaGetSymbolAddress((void**)&TXh, g_TXh);
    cudaGetSymbolAddress((void**)&TXl, g_TXl);
    cudaGetSymbolAddress((void**)&Xh,  g_Xh);
    cudaGetSymbolAddress((void**)&Xl,  g_Xl);
    cudaGetSymbolAddress((void**)&WTh, g_WTh);
    cudaGetSymbolAddress((void**)&WTl, g_WTl);
    cudaGetSymbolAddress((void**)&Wph, g_Wph);
    cudaGetSymbolAddress((void**)&Wpl, g_Wpl);

    cudaFuncSetAttribute(k_mgemm, cudaFuncAttributeMaxDynamicSharedMemorySize, 2 * GBUF);

    // --- zero-init FIRST (these buffers are then populated below) ---
    k_zero_f4<<<2048, 256>>>((float4*)TXh, (long)MPAD * 96);
    k_zero_f4<<<2048, 256>>>((float4*)TXl, (long)MPAD * 96);
    k_zero_f4<<<1024, 256>>>((float4*)Xh,  (long)MPAD * TT * 16);
    k_zero_f4<<<1024, 256>>>((float4*)Xl,  (long)MPAD * TT * 16);
    k_zero_f4<<<512,  256>>>((float4*)Cst, (long)MPAD * 32);

    // --- graph preprocessing + weight/input prep ---
    k_detect<<<1, 1>>>(edges);
    k_convert<<<(2 * EE + 255) / 256, 256>>>(edges);
    k_zero_counts<<<(2 * NN + 255) / 256, 256>>>();
    k_count<<<(EE + 255) / 256, 256>>>();
    k_dinv<<<(NN + 255) / 256, 256>>>();
    k_scan<<<1, 1024>>>();
    k_fill<<<(EE + 255) / 256, 256>>>();
    k_prep<<<(512 * 768 + 255) / 256, 256>>>(convW, convb, gb, Wpool);
    k_splitX<<<(TT * NN * 128 + 255) / 256, 256>>>(X);

    const int propBlocks = (NN + 3) / 4;   // 4 warps/block

    for (int t = 0; t < TT; ++t) {
        // Xp = X_t @ W_pool^T -> TX block 0 (fp32) + TXh/TXl block 0
        k_mgemm<<<dim3(1, MPAD / 128), 256, 2 * GBUF>>>(
            Xh + (size_t)t * MPAD * 128, Xl + (size_t)t * MPAD * 128, 128,
            Wph, Wpl, 128, 128, TX, LDTX, TXh, TXl);
        // Chebyshev level 1: Tx1x = L@Xp ; Tx1h = L@H
        k_prop2<<<propBlocks, 128>>>(0, 128, -1, 384, 512, -1, 1.f, (t > 0) ? 1 : 0);
        // Chebyshev level 2: Tx2 = 2*L@Tx1 - Tx0
        k_prop2<<<propBlocks, 128>>>(128, 256, 0, 512, 640, 384, 2.f, (t > 0) ? 1 : 0);
        // Z = TX(N x 768) @ W_all(768 x 512)
        k_mgemm<<<dim3(4, MPAD / 128), 256, 2 * GBUF>>>(
            TXh, TXl, 768, WTh, WTl, 768, 768, Z, 512, nullptr, nullptr);
        // gates
        k_gate<<<(NN * 128 + 255) / 256, 256>>>(pw, out, t);
    }
}

// round 5
// speedup vs baseline: 2.3712x; 1.0723x over previous
#include <cuda_runtime.h>
#include <cuda_bf16.h>
#include <math.h>
#include <stdint.h>

// Problem constants
#define NN   50000
#define TT   4
#define CC   128
#define FF   128
#define KK   3
#define EE   800000
#define MPAD 50048          // 391 * 128
#define NB   384            // basis width per path (3 blocks of 128)

#define SWZ(b) ((b) ^ (((b) >> 3) & 0x70))

// ---------------------------------------------------------------------------
// Device scratch
// ---------------------------------------------------------------------------
__device__ __align__(16) float        g_Bx32[(size_t)TT * MPAD * NB];  // x-basis fp32 (Xp|Tx1x|Tx2x), Tx2x slot unused
__device__ __align__(16) __nv_bfloat16 g_Bxh[(size_t)TT * MPAD * NB];
__device__ __align__(16) __nv_bfloat16 g_Bxl[(size_t)TT * MPAD * NB];
__device__ __align__(16) float        g_Bh32[(size_t)MPAD * NB];       // h-basis fp32
__device__ __align__(16) __nv_bfloat16 g_Bhh[(size_t)MPAD * NB];
__device__ __align__(16) __nv_bfloat16 g_Bhl[(size_t)MPAD * NB];
__device__ __align__(16) float g_Z  [(size_t)MPAD * 512];
__device__ __align__(16) float g_Cst[(size_t)MPAD * 128];
__device__ __align__(16) __nv_bfloat16 g_Xh[(size_t)TT * MPAD * 128];
__device__ __align__(16) __nv_bfloat16 g_Xl[(size_t)TT * MPAD * 128];
__device__ __align__(16) __nv_bfloat16 g_WTh[512 * 768];    // B main GEMM, [n][k]
__device__ __align__(16) __nv_bfloat16 g_WTl[512 * 768];
__device__ __align__(16) __nv_bfloat16 g_Wph[128 * 128];    // B pool GEMM, [c][f]
__device__ __align__(16) __nv_bfloat16 g_Wpl[128 * 128];
__device__ __align__(16) float g_bias[512];
__device__ int   g_es[EE];
__device__ int   g_ed[EE];
__device__ int   g_deg[NN];
__device__ int   g_cnt[NN];
__device__ float g_dinv[NN];
__device__ int   g_rowptr[NN + 1];
__device__ int   g_cursor[NN];
__device__ int   g_col[EE];
__device__ float g_val[EE];
__device__ int   g_flag64;

__device__ __forceinline__ void split_bf16(float x, __nv_bfloat16& h, __nv_bfloat16& l) {
    h = __float2bfloat16(x);
    l = __float2bfloat16(x - __bfloat162float(h));
}
__device__ __forceinline__ uint32_t smem_u32(const void* p) {
    uint32_t a;
    asm("{ .reg .u64 t; cvta.to.shared.u64 t, %1; cvt.u32.u64 %0, t; }" : "=r"(a) : "l"(p));
    return a;
}

// ---------------------------------------------------------------------------
// Launch 1: fused init — detect int64/int32, zero recurrent buffers + counters
// ---------------------------------------------------------------------------
__global__ void k_init(const void* edges) {
    if (blockIdx.x == 0 && threadIdx.x == 0) {
        const long long* p = (const long long*)edges;
        int ok = 1;
        for (int i = 0; i < 512; ++i) {
            long long v = p[i];
            if (v < 0 || v >= NN) { ok = 0; break; }
        }
        g_flag64 = ok;
    }
    const long s0 = (long)MPAD * NB / 8;   // Bhh as float4 (bf16: NB*2B/16)
    const long s1 = s0;                    // Bhl
    const long s2 = (long)MPAD * 32;       // Cst f4
    const long s3 = 2 * (NN / 4);          // deg + cnt as int4
    const long s4 = (long)TT * 2 * 768;    // X pad rows f4 (48*128*2B/16=768 per t per buf)
    const long total = s0 + s1 + s2 + s3 + s4;
    const float4 z4 = make_float4(0.f, 0.f, 0.f, 0.f);
    long i = (long)blockIdx.x * blockDim.x + threadIdx.x;
    long stride = (long)gridDim.x * blockDim.x;
    for (; i < total; i += stride) {
        if (i < s0) ((float4*)g_Bhh)[i] = z4;
        else if (i < s0 + s1) ((float4*)g_Bhl)[i - s0] = z4;
        else if (i < s0 + s1 + s2) ((float4*)g_Cst)[i - s0 - s1] = z4;
        else if (i < s0 + s1 + s2 + s3) {
            long j = i - s0 - s1 - s2;
            if (j < NN / 4) ((int4*)g_deg)[j] = make_int4(0, 0, 0, 0);
            else            ((int4*)g_cnt)[j - NN / 4] = make_int4(0, 0, 0, 0);
        } else {
            long j = i - s0 - s1 - s2 - s3;
            long t = j / 1536, r = j % 1536;
            long buf = r / 768, k = r % 768;
            char* base = (char*)(buf ? g_Xl : g_Xh);
            *(float4*)(base + ((size_t)(t * MPAD + NN) * 128) * 2 + k * 16) = z4;
        }
    }
}

// Launch 2: convert + degree counting
__global__ void k_convcount(const void* edges) {
    int i = blockIdx.x * blockDim.x + threadIdx.x;
    if (i >= 2 * EE) return;
    int v;
    if (g_flag64) v = (int)((const long long*)edges)[i];
    else          v = ((const int*)edges)[i];
    if (i < EE) { g_es[i] = v; atomicAdd(&g_deg[v], 1); }
    else        { g_ed[i - EE] = v; atomicAdd(&g_cnt[v], 1); }
}

// Launch 3: block 0 = exclusive scan of cnt; other blocks = dinv
__global__ void k_scan_dinv() {
    if (blockIdx.x == 0) {
        __shared__ int sh[1024];
        const int t = threadIdx.x;
        const int CH = (NN + 1023) / 1024;
        int s = 0;
        int base0 = t * CH;
        for (int j = 0; j < CH; ++j) { int idx = base0 + j; if (idx < NN) s += g_cnt[idx]; }
        sh[t] = s;
        __syncthreads();
        for (int off = 1; off < 1024; off <<= 1) {
            int v = (t >= off) ? sh[t - off] : 0;
            __syncthreads();
            sh[t] += v;
            __syncthreads();
        }
        int run = (t == 0) ? 0 : sh[t - 1];
        for (int j = 0; j < CH; ++j) {
            int idx = base0 + j;
            if (idx < NN) { g_rowptr[idx] = run; g_cursor[idx] = run; run += g_cnt[idx]; }
        }
        if (t == 1023) g_rowptr[NN] = EE;
    } else {
        int i = (blockIdx.x - 1) * 1024 + threadIdx.x;
        if (i < NN) {
            int d = g_deg[i];
            g_dinv[i] = (d > 0) ? rsqrtf((float)d) : 0.0f;
        }
    }
}

// Launch 4: CSR fill + weight prep + X split (fused, block ranges)
#define FPS_FILL_BLK   3125
#define FPS_PREP_BLK   1536
#define FPS_SPLIT_BLK  100096
__global__ void k_fps(const float* __restrict__ X,
                      const float* __restrict__ convW, const float* __restrict__ convb,
                      const float* __restrict__ gateb, const float* __restrict__ Wpool) {
    int b = blockIdx.x;
    if (b < FPS_FILL_BLK) {
        int i = b * 256 + threadIdx.x;
        if (i >= EE) return;
        int s = g_es[i], d = g_ed[i];
        int pos = atomicAdd(&g_cursor[d], 1);
        g_col[pos] = s;
        g_val[pos] = -(g_dinv[s] * g_dinv[d]);
    } else if (b < FPS_FILL_BLK + FPS_PREP_BLK) {
        int i = (b - FPS_FILL_BLK) * 256 + threadIdx.x;
        if (i < 512 * 768) {
            int cc = i / 768, r = i % 768;
            int kblk = r >> 7, rin = r & 127;
            int gate = cc >> 7, ch = cc & 127;
            int k   = kblk % 3;
            int idx = (kblk < 3) ? (2 * gate) : (2 * gate + 1);
            float v = convW[((size_t)(idx * KK + k)) * CC * CC + rin * CC + ch];
            __nv_bfloat16 h, l; split_bf16(v, h, l);
            g_WTh[i] = h; g_WTl[i] = l;
        }
        if (i < 512) {
            int gate = i / 128, c = i % 128;
            g_bias[i] = convb[(2 * gate) * CC + c] + convb[(2 * gate + 1) * CC + c] + gateb[gate * CC + c];
        }
        if (i < 128 * 128) {
            __nv_bfloat16 h, l; split_bf16(Wpool[i], h, l);
            g_Wph[i] = h; g_Wpl[i] = l;
        }
    } else {
        int i = (b - FPS_FILL_BLK - FPS_PREP_BLK) * 256 + threadIdx.x;
        if (i >= TT * NN * 128) return;
        int t = i / (NN * 128);
        int r = i - t * (NN * 128);
        int n = r >> 7, f = r & 127;
        __nv_bfloat16 h, l; split_bf16(X[i], h, l);
        size_t o = ((size_t)t * MPAD + n) * 128 + f;
        g_Xh[o] = h; g_Xl[o] = l;
    }
}

// ---------------------------------------------------------------------------
// mma.sync bf16-split GEMM, 3-stage cp.async pipeline.
// A comes from two source pairs: chunks [0,kcx) from Axh/Axl, rest from Ahh/Ahl
// (both with row stride lda). B [Ncols][K] row-major. 3 products.
// ---------------------------------------------------------------------------
__device__ __forceinline__ void ldsm4(uint32_t addr, uint32_t* r) {
    asm volatile("ldmatrix.sync.aligned.m8n8.x4.shared.b16 {%0,%1,%2,%3}, [%4];"
        : "=r"(r[0]), "=r"(r[1]), "=r"(r[2]), "=r"(r[3]) : "r"(addr));
}
__device__ __forceinline__ void mma16816(float* d, const uint32_t* a, const uint32_t* b) {
    asm volatile("mma.sync.aligned.m16n8k16.row.col.f32.bf16.bf16.f32 "
        "{%0,%1,%2,%3}, {%4,%5,%6,%7}, {%8,%9}, {%0,%1,%2,%3};"
        : "+f"(d[0]), "+f"(d[1]), "+f"(d[2]), "+f"(d[3])
        : "r"(a[0]), "r"(a[1]), "r"(a[2]), "r"(a[3]), "r"(b[0]), "r"(b[1]));
}
__device__ __forceinline__ void cp16(uint32_t dst, const void* src) {
    asm volatile("cp.async.cg.shared.global [%0], [%1], 16;" :: "r"(dst), "l"(src));
}

#define GBUF   65536u   // per stage: Ah 16K | Al 16K | Bh 16K | Bl 16K
#define STAGES 3

__global__ void __launch_bounds__(256) k_mgemm(
    const __nv_bfloat16* __restrict__ Axh, const __nv_bfloat16* __restrict__ Axl,
    const __nv_bfloat16* __restrict__ Ahh, const __nv_bfloat16* __restrict__ Ahl,
    int kcx, int lda,
    const __nv_bfloat16* __restrict__ Bh, const __nv_bfloat16* __restrict__ Bl, int ldb,
    int K,
    float* __restrict__ outF, int ldc,
    __nv_bfloat16* __restrict__ oBh, __nv_bfloat16* __restrict__ oBl, int ldo)
{
    extern __shared__ char sm[];
    const int tid  = threadIdx.x;
    const int wid  = tid >> 5;
    const int lane = tid & 31;
    const int rowTile = blockIdx.y * 128;
    const int colTile = blockIdx.x * 128;
    const int warp_m = (wid >> 2) * 64;
    const int warp_n = (wid & 3) * 32;
    const uint32_t smb = smem_u32(sm);
    const int nch = K >> 6;

    float d[4][4][4];
#pragma unroll
    for (int a = 0; a < 4; ++a)
#pragma unroll
        for (int b = 0; b < 4; ++b)
#pragma unroll
            for (int q = 0; q < 4; ++q) d[a][b][q] = 0.f;

    auto issue = [&](int c) {
        const uint32_t dstBase = smb + (uint32_t)(c % STAGES) * GBUF;
        const int ca = (c < kcx) ? c : c - kcx;
#pragma unroll
        for (int it = 0; it < 16; ++it) {
            int i  = tid + it * 256;
            int sp = i >> 10;                 // 0 Ah,1 Al,2 Bh,3 Bl
            int r  = (i & 1023) >> 3;
            int f  = i & 7;
            const void* src;
            if (sp < 2) {
                const __nv_bfloat16* ab = (c < kcx) ? (sp ? Axl : Axh) : (sp ? Ahl : Ahh);
                src = ab + (size_t)(rowTile + r) * lda + ca * 64 + f * 8;
            } else {
                src = ((sp == 2) ? Bh : Bl) + (size_t)(colTile + r) * ldb + c * 64 + f * 8;
            }
            cp16(dstBase + sp * 16384u + SWZ((uint32_t)(r * 128 + f * 16)), src);
        }
        asm volatile("cp.async.commit_group;" ::: "memory");
    };

    issue(0);
    if (nch > 1) issue(1);
    if (nch > 2) issue(2);

    for (int c = 0; c < nch; ++c) {
        int w = nch - 1 - c;
        if (w >= 2)      asm volatile("cp.async.wait_group 2;" ::: "memory");
        else if (w == 1) asm volatile("cp.async.wait_group 1;" ::: "memory");
        else             asm volatile("cp.async.wait_group 0;" ::: "memory");
        __syncthreads();

        const uint32_t sm0 = smb + (uint32_t)(c % STAGES) * GBUF;
        const int laneRowA = warp_m + (lane & 15);
        const uint32_t kbA = (uint32_t)((lane >> 4) * 16);
        const int nrowB = warp_n + (lane & 7) + ((lane >> 4) << 3);
        const uint32_t kbB = (uint32_t)(((lane >> 3) & 1) * 16);

#pragma unroll
        for (int ks = 0; ks < 4; ++ks) {
            uint32_t ah[4][4], al[4][4], bh[4][2], bl[4][2];
#pragma unroll
            for (int mt = 0; mt < 4; ++mt) {
                uint32_t off = SWZ((uint32_t)((laneRowA + mt * 16) * 128) + ks * 32 + kbA);
                ldsm4(sm0 + off, ah[mt]);
                ldsm4(sm0 + 16384u + off, al[mt]);
            }
#pragma unroll
            for (int np = 0; np < 2; ++np) {
                uint32_t off = SWZ((uint32_t)((nrowB + np * 16) * 128) + ks * 32 + kbB);
                uint32_t r0[4], r1[4];
                ldsm4(sm0 + 32768u + off, r0);
                ldsm4(sm0 + 49152u + off, r1);
                bh[2 * np][0] = r0[0]; bh[2 * np][1] = r0[1];
                bh[2 * np + 1][0] = r0[2]; bh[2 * np + 1][1] = r0[3];
                bl[2 * np][0] = r1[0]; bl[2 * np][1] = r1[1];
                bl[2 * np + 1][0] = r1[2]; bl[2 * np + 1][1] = r1[3];
            }
#pragma unroll
            for (int mt = 0; mt < 4; ++mt)
#pragma unroll
                for (int nt = 0; nt < 4; ++nt) {
                    mma16816(d[mt][nt], ah[mt], bh[nt]);
                    mma16816(d[mt][nt], ah[mt], bl[nt]);
                    mma16816(d[mt][nt], al[mt], bh[nt]);
                }
        }
        if (c + STAGES < nch) {
            __syncthreads();
            issue(c + STAGES);
        }
    }

    // --- epilogue ---
#pragma unroll
    for (int mt = 0; mt < 4; ++mt) {
        int m0 = rowTile + warp_m + mt * 16 + (lane >> 2);
#pragma unroll
        for (int nt = 0; nt < 4; ++nt) {
            int n0 = colTile + warp_n + nt * 8 + (lane & 3) * 2;
#pragma unroll
            for (int half = 0; half < 2; ++half) {
                int m = m0 + half * 8;
                float v0 = d[mt][nt][half * 2], v1 = d[mt][nt][half * 2 + 1];
                *(float2*)&outF[(size_t)m * ldc + n0] = make_float2(v0, v1);
                if (oBh) {
                    __nv_bfloat16 h0, l0, h1, l1;
                    split_bf16(v0, h0, l0); split_bf16(v1, h1, l1);
                    size_t bo = (size_t)m * ldo + n0;
                    *(__nv_bfloat162*)&oBh[bo] = __halves2bfloat162(h0, h1);
                    *(__nv_bfloat162*)&oBl[bo] = __halves2bfloat162(l0, l1);
                }
            }
        }
    }
}

// ---------------------------------------------------------------------------
// Chebyshev propagation. Level 1: out = L@in (fp32 + bf16 h/l).
// Level 2: out = 2*L@in - sub (bf16 h/l only). Warp per (t, node).
// Row stride NB; t-slice stride MPAD*NB.
// ---------------------------------------------------------------------------
__global__ void k_prop1(const float* __restrict__ in32, float* __restrict__ out32,
                        __nv_bfloat16* __restrict__ oh, __nv_bfloat16* __restrict__ ol,
                        int nWarp)
{
    int gw = (blockIdx.x * blockDim.x + threadIdx.x) >> 5;
    int lane = threadIdx.x & 31;
    if (gw >= nWarp) return;
    int t = gw / NN;
    int n = gw - t * NN;
    size_t so = (size_t)t * MPAD * NB;

    int start = g_rowptr[n], end = g_rowptr[n + 1];
    float4 acc = make_float4(0.f, 0.f, 0.f, 0.f);
#pragma unroll 2
    for (int e = start; e < end; ++e) {
        int   s = g_col[e];
        float w = g_val[e];
        float4 v = ((const float4*)(in32 + so + (size_t)s * NB))[lane];
        acc.x += w * v.x; acc.y += w * v.y; acc.z += w * v.z; acc.w += w * v.w;
    }
    size_t ro = so + (size_t)n * NB;
    ((float4*)(out32 + ro))[lane] = acc;
    __nv_bfloat16 h0, l0, h1, l1, h2, l2, h3, l3;
    split_bf16(acc.x, h0, l0); split_bf16(acc.y, h1, l1);
    split_bf16(acc.z, h2, l2); split_bf16(acc.w, h3, l3);
    *(__nv_bfloat162*)(oh + ro + lane * 4)     = __halves2bfloat162(h0, h1);
    *(__nv_bfloat162*)(oh + ro + lane * 4 + 2) = __halves2bfloat162(h2, h3);
    *(__nv_bfloat162*)(ol + ro + lane * 4)     = __halves2bfloat162(l0, l1);
    *(__nv_bfloat162*)(ol + ro + lane * 4 + 2) = __halves2bfloat162(l2, l3);
}

__global__ void k_prop2k(const float* __restrict__ in32, const float* __restrict__ sub32,
                         __nv_bfloat16* __restrict__ oh, __nv_bfloat16* __restrict__ ol,
                         int nWarp)
{
    int gw = (blockIdx.x * blockDim.x + threadIdx.x) >> 5;
    int lane = threadIdx.x & 31;
    if (gw >= nWarp) return;
    int t = gw / NN;
    int n = gw - t * NN;
    size_t so = (size_t)t * MPAD * NB;

    int start = g_rowptr[n], end = g_rowptr[n + 1];
    float4 acc = make_float4(0.f, 0.f, 0.f, 0.f);
#pragma unroll 2
    for (int e = start; e < end; ++e) {
        int   s = g_col[e];
        float w = g_val[e];
        float4 v = ((const float4*)(in32 + so + (size_t)s * NB))[lane];
        acc.x += w * v.x; acc.y += w * v.y; acc.z += w * v.z; acc.w += w * v.w;
    }
    float4 sv = ((const float4*)(sub32 + so + (size_t)n * NB))[lane];
    float4 o = make_float4(2.f * acc.x - sv.x, 2.f * acc.y - sv.y,
                           2.f * acc.z - sv.z, 2.f * acc.w - sv.w);
    size_t ro = so + (size_t)n * NB;
    __nv_bfloat16 h0, l0, h1, l1, h2, l2, h3, l3;
    split_bf16(o.x, h0, l0); split_bf16(o.y, h1, l1);
    split_bf16(o.z, h2, l2); split_bf16(o.w, h3, l3);
    *(__nv_bfloat162*)(oh + ro + lane * 4)     = __halves2bfloat162(h0, h1);
    *(__nv_bfloat162*)(oh + ro + lane * 4 + 2) = __halves2bfloat162(h2, h3);
    *(__nv_bfloat162*)(ol + ro + lane * 4)     = __halves2bfloat162(l0, l1);
    *(__nv_bfloat162*)(ol + ro + lane * 4 + 2) = __halves2bfloat162(l2, l3);
}

// ---------------------------------------------------------------------------
// Gate fusion: writes H into h-basis block 0 (fp32 + bf16 h/l) + output
// ---------------------------------------------------------------------------
__device__ __forceinline__ float sigmoidf(float x) { return 1.f / (1.f + expf(-x)); }

__global__ void k_gate(const float* __restrict__ pw, float* __restrict__ out, int t) {
    int i = blockIdx.x * blockDim.x + threadIdx.x;
    if (i >= NN * 128) return;
    int n = i >> 7, c = i & 127;

    const float* z = &g_Z[(size_t)n * 512];
    float zi = z[c], zf = z[128 + c], zc = z[256 + c], zo = z[384 + c];
    float cold = g_Cst[(size_t)n * 128 + c];

    float I  = sigmoidf(zi + g_bias[c]       + pw[c]       * cold);
    float F  = sigmoidf(zf + g_bias[128 + c] + pw[128 + c] * cold);
    float Tc = tanhf  (zc + g_bias[256 + c]);
    float cnew = F * cold + I * Tc;
    float O  = sigmoidf(zo + g_bias[384 + c] + pw[256 + c] * cnew);
    float h  = O * tanhf(cnew);

    g_Cst[(size_t)n * 128 + c] = cnew;
    g_Bh32[(size_t)n * NB + c] = h;
    __nv_bfloat16 hh, hl; split_bf16(h, hh, hl);
    g_Bhh[(size_t)n * NB + c] = hh;
    g_Bhl[(size_t)n * NB + c] = hl;
    out[((size_t)n * TT + t) * CC + c] = h;
}

// ---------------------------------------------------------------------------
// Host launcher
// ---------------------------------------------------------------------------
extern "C" void kernel_launch(void* const* d_in, const int* in_sizes, int n_in,
                              void* d_out, int out_size)
{
    const float* X     = (const float*)d_in[0];
    const void*  edges = d_in[1];
    const float* Wpool = (const float*)d_in[2];
    const float* convW = (const float*)d_in[3];
    const float* convb = (const float*)d_in[4];
    const float* pw    = (const float*)d_in[5];
    const float* gb    = (const float*)d_in[6];
    float* out = (float*)d_out;

    float *Bx32, *Bh32, *Z;
    __nv_bfloat16 *Bxh, *Bxl, *Bhh, *Bhl, *Xh, *Xl, *WTh, *WTl, *Wph, *Wpl;
    cudaGetSymbolAddress((void**)&Bx32, g_Bx32);
    cudaGetSymbolAddress((void**)&Bh32, g_Bh32);
    cudaGetSymbolAddress((void**)&Z,    g_Z);
    cudaGetSymbolAddress((void**)&Bxh,  g_Bxh);
    cudaGetSymbolAddress((void**)&Bxl,  g_Bxl);
    cudaGetSymbolAddress((void**)&Bhh,  g_Bhh);
    cudaGetSymbolAddress((void**)&Bhl,  g_Bhl);
    cudaGetSymbolAddress((void**)&Xh,   g_Xh);
    cudaGetSymbolAddress((void**)&Xl,   g_Xl);
    cudaGetSymbolAddress((void**)&WTh,  g_WTh);
    cudaGetSymbolAddress((void**)&WTl,  g_WTl);
    cudaGetSymbolAddress((void**)&Wph,  g_Wph);
    cudaGetSymbolAddress((void**)&Wpl,  g_Wpl);

    cudaFuncSetAttribute(k_mgemm, cudaFuncAttributeMaxDynamicSharedMemorySize, STAGES * GBUF);

    const size_t SLC = (size_t)MPAD * NB;   // t-slice stride (elements)

    // 1-4: preprocessing
    k_init<<<8192, 256>>>(edges);
    k_convcount<<<(2 * EE + 255) / 256, 256>>>(edges);
    k_scan_dinv<<<50, 1024>>>();
    k_fps<<<FPS_FILL_BLK + FPS_PREP_BLK + FPS_SPLIT_BLK, 256>>>(X, convW, convb, gb, Wpool);

    // 5: pool GEMM, all timesteps batched: Xp = X @ Wpool^T -> Bx32/Bxh/Bxl block 0
    k_mgemm<<<dim3(1, TT * MPAD / 128), 256, STAGES * GBUF>>>(
        Xh, Xl, Xh, Xl, 99, 128, Wph, Wpl, 128, 128,
        Bx32, NB, Bxh, Bxl, NB);

    // 6-7: x-path Chebyshev basis, all timesteps batched
    k_prop1<<<TT * NN / 4, 128>>>(Bx32, Bx32 + 128, Bxh + 128, Bxl + 128, TT * NN);
    k_prop2k<<<TT * NN / 4, 128>>>(Bx32 + 128, Bx32, Bxh + 256, Bxl + 256, TT * NN);

    // recurrent loop
    for (int t = 0; t < TT; ++t) {
        if (t > 0) {
            k_prop1<<<NN / 4, 128>>>(Bh32, Bh32 + 128, Bhh + 128, Bhl + 128, NN);
            k_prop2k<<<NN / 4, 128>>>(Bh32 + 128, Bh32, Bhh + 256, Bhl + 256, NN);
        }
        // Z = [x-basis_t | h-basis] (N x 768) @ W_all^T (768 x 512)
        k_mgemm<<<dim3(4, MPAD / 128), 256, STAGES * GBUF>>>(
            Bxh + (size_t)t * SLC, Bxl + (size_t)t * SLC, Bhh, Bhl, 6, NB,
            WTh, WTl, 768, 768, Z, 512, nullptr, nullptr, 0);
        k_gate<<<(NN * 128 + 255) / 256, 256>>>(pw, out, t);
    }
}

// round 6
// speedup vs baseline: 3.0058x; 1.2676x over previous
#include <cuda_runtime.h>
#include <cuda_fp16.h>
#include <math.h>
#include <stdint.h>

// Problem constants
#define NN   50000
#define TT   4
#define CC   128
#define FF   128
#define KK   3
#define EE   800000
#define MPAD 50048          // 391 * 128
#define NB   384            // fp16 basis row stride (3 blocks of 128)
#define S32  256            // fp32 basis row stride (2 blocks: Xp|Tx1)

#define SWZ(b) ((b) ^ (((b) >> 3) & 0x70))

// ---------------------------------------------------------------------------
// Device scratch
// ---------------------------------------------------------------------------
__device__ __align__(16) float  g_Bx32[(size_t)TT * MPAD * S32];  // x: Xp|Tx1x fp32
__device__ __align__(16) __half g_Bxf [(size_t)TT * MPAD * NB];   // x basis fp16
__device__ __align__(16) float  g_Bh32[(size_t)MPAD * S32];       // h: H|Tx1h fp32
__device__ __align__(16) __half g_Bhf [(size_t)MPAD * NB];        // h basis fp16
__device__ __align__(16) float  g_Z   [(size_t)MPAD * 512];
__device__ __align__(16) float  g_Cst [(size_t)MPAD * 128];
__device__ __align__(16) __half g_Xf  [(size_t)TT * MPAD * 128];  // X fp16
__device__ __align__(16) __half g_WTh [512 * 768];                // W hi, [n][k]
__device__ __align__(16) __half g_WTl [512 * 768];                // W lo
__device__ __align__(16) __half g_Wph [128 * 128];                // Wpool hi [c][f]
__device__ __align__(16) __half g_Wpl [128 * 128];
__device__ __align__(16) float  g_bias[512];
__device__ int   g_es[EE];
__device__ int   g_ed[EE];
__device__ int   g_deg[NN];
__device__ int   g_cnt[NN];
__device__ float g_dinv[NN];
__device__ int   g_rowptr[NN + 1];
__device__ int   g_cursor[NN];
__device__ int   g_col[EE];
__device__ float g_val[EE];
__device__ int   g_flag64;

__device__ __forceinline__ void split_h(float x, __half& h, __half& l) {
    h = __float2half_rn(x);
    l = __float2half_rn(x - __half2float(h));
}
__device__ __forceinline__ uint32_t pack_h2(float a, float b) {
    __half2 h = __floats2half2_rn(a, b);
    return *(uint32_t*)&h;
}
__device__ __forceinline__ uint32_t smem_u32(const void* p) {
    uint32_t a;
    asm("{ .reg .u64 t; cvta.to.shared.u64 t, %1; cvt.u32.u64 %0, t; }" : "=r"(a) : "l"(p));
    return a;
}

// ---------------------------------------------------------------------------
// Launch 1: fused init — int64 detect + zero Bhf/Cst/counters/Xf pads
// ---------------------------------------------------------------------------
__global__ void k_init(const void* edges) {
    if (blockIdx.x == 0 && threadIdx.x == 0) {
        const long long* p = (const long long*)edges;
        int ok = 1;
        for (int i = 0; i < 512; ++i) {
            long long v = p[i];
            if (v < 0 || v >= NN) { ok = 0; break; }
        }
        g_flag64 = ok;
    }
    const long s0 = (long)MPAD * 48;      // Bhf (fp16, NB*2B/16)
    const long s1 = (long)MPAD * 32;      // Cst f4
    const long s2 = 2 * (NN / 4);         // deg + cnt int4
    const long s3 = (long)TT * 768;       // Xf pad rows (48 rows * 256B / 16 per t)
    const long total = s0 + s1 + s2 + s3;
    const float4 z4 = make_float4(0.f, 0.f, 0.f, 0.f);
    long i = (long)blockIdx.x * blockDim.x + threadIdx.x;
    long stride = (long)gridDim.x * blockDim.x;
    for (; i < total; i += stride) {
        if (i < s0) ((float4*)g_Bhf)[i] = z4;
        else if (i < s0 + s1) ((float4*)g_Cst)[i - s0] = z4;
        else if (i < s0 + s1 + s2) {
            long j = i - s0 - s1;
            if (j < NN / 4) ((int4*)g_deg)[j] = make_int4(0, 0, 0, 0);
            else            ((int4*)g_cnt)[j - NN / 4] = make_int4(0, 0, 0, 0);
        } else {
            long j = i - s0 - s1 - s2;
            long t = j / 768, k = j % 768;
            *(float4*)((char*)g_Xf + ((size_t)(t * MPAD + NN) * 128) * 2 + k * 16) = z4;
        }
    }
}

// Launch 2: convert + degree counting
__global__ void k_convcount(const void* edges) {
    int i = blockIdx.x * blockDim.x + threadIdx.x;
    if (i >= 2 * EE) return;
    int v;
    if (g_flag64) v = (int)((const long long*)edges)[i];
    else          v = ((const int*)edges)[i];
    if (i < EE) { g_es[i] = v; atomicAdd(&g_deg[v], 1); }
    else        { g_ed[i - EE] = v; atomicAdd(&g_cnt[v], 1); }
}

// Launch 3: block 0 = exclusive scan; others = dinv
__global__ void k_scan_dinv() {
    if (blockIdx.x == 0) {
        __shared__ int sh[1024];
        const int t = threadIdx.x;
        const int CH = (NN + 1023) / 1024;
        int s = 0;
        int base0 = t * CH;
        for (int j = 0; j < CH; ++j) { int idx = base0 + j; if (idx < NN) s += g_cnt[idx]; }
        sh[t] = s;
        __syncthreads();
        for (int off = 1; off < 1024; off <<= 1) {
            int v = (t >= off) ? sh[t - off] : 0;
            __syncthreads();
            sh[t] += v;
            __syncthreads();
        }
        int run = (t == 0) ? 0 : sh[t - 1];
        for (int j = 0; j < CH; ++j) {
            int idx = base0 + j;
            if (idx < NN) { g_rowptr[idx] = run; g_cursor[idx] = run; run += g_cnt[idx]; }
        }
        if (t == 1023) g_rowptr[NN] = EE;
    } else {
        int i = (blockIdx.x - 1) * 1024 + threadIdx.x;
        if (i < NN) {
            int d = g_deg[i];
            g_dinv[i] = (d > 0) ? rsqrtf((float)d) : 0.0f;
        }
    }
}

// Launch 4: CSR fill + weight prep + vectorized X->fp16
#define FPS_FILL_BLK   3125
#define FPS_PREP_BLK   1536
#define FPS_SPLIT_BLK  25000   // TT*NN*128/4/256
__global__ void k_fps(const float* __restrict__ X,
                      const float* __restrict__ convW, const float* __restrict__ convb,
                      const float* __restrict__ gateb, const float* __restrict__ Wpool) {
    int b = blockIdx.x;
    if (b < FPS_FILL_BLK) {
        int i = b * 256 + threadIdx.x;
        if (i >= EE) return;
        int s = g_es[i], d = g_ed[i];
        int pos = atomicAdd(&g_cursor[d], 1);
        g_col[pos] = s;
        g_val[pos] = -(g_dinv[s] * g_dinv[d]);
    } else if (b < FPS_FILL_BLK + FPS_PREP_BLK) {
        int i = (b - FPS_FILL_BLK) * 256 + threadIdx.x;
        if (i < 512 * 768) {
            int cc = i / 768, r = i % 768;
            int kblk = r >> 7, rin = r & 127;
            int gate = cc >> 7, ch = cc & 127;
            int k   = kblk % 3;
            int idx = (kblk < 3) ? (2 * gate) : (2 * gate + 1);
            float v = convW[((size_t)(idx * KK + k)) * CC * CC + rin * CC + ch];
            __half h, l; split_h(v, h, l);
            g_WTh[i] = h; g_WTl[i] = l;
        }
        if (i < 512) {
            int gate = i / 128, c = i % 128;
            g_bias[i] = convb[(2 * gate) * CC + c] + convb[(2 * gate + 1) * CC + c] + gateb[gate * CC + c];
        }
        if (i < 128 * 128) {
            __half h, l; split_h(Wpool[i], h, l);
            g_Wph[i] = h; g_Wpl[i] = l;
        }
    } else {
        int i4 = (b - FPS_FILL_BLK - FPS_PREP_BLK) * 256 + threadIdx.x;
        if (i4 >= TT * NN * 32) return;
        int e = i4 * 4;
        int t = e / (NN * 128);
        int r = e - t * (NN * 128);
        int n = r >> 7, f = r & 127;
        float4 v = *(const float4*)(X + e);
        uint2 u;
        u.x = pack_h2(v.x, v.y);
        u.y = pack_h2(v.z, v.w);
        *(uint2*)(g_Xf + ((size_t)t * MPAD + n) * 128 + f) = u;
    }
}

// ---------------------------------------------------------------------------
// mma.sync fp16 2-product GEMM, 4-stage cp.async pipeline.
// out[M, Ncols] = A[M,K] @ (Bh+Bl)^T; A fp16 single, B fp16 hi/lo split.
// A from two sources: chunks [0,kcx) from Ax, rest from Ah2 (same lda).
// CTA 128x128, warp 64x32 (8 warps), K chunk 64.
// ---------------------------------------------------------------------------
__device__ __forceinline__ void ldsm4(uint32_t addr, uint32_t* r) {
    asm volatile("ldmatrix.sync.aligned.m8n8.x4.shared.b16 {%0,%1,%2,%3}, [%4];"
        : "=r"(r[0]), "=r"(r[1]), "=r"(r[2]), "=r"(r[3]) : "r"(addr));
}
__device__ __forceinline__ void mma16816(float* d, const uint32_t* a, const uint32_t* b) {
    asm volatile("mma.sync.aligned.m16n8k16.row.col.f32.f16.f16.f32 "
        "{%0,%1,%2,%3}, {%4,%5,%6,%7}, {%8,%9}, {%0,%1,%2,%3};"
        : "+f"(d[0]), "+f"(d[1]), "+f"(d[2]), "+f"(d[3])
        : "r"(a[0]), "r"(a[1]), "r"(a[2]), "r"(a[3]), "r"(b[0]), "r"(b[1]));
}
__device__ __forceinline__ void cp16(uint32_t dst, const void* src) {
    asm volatile("cp.async.cg.shared.global [%0], [%1], 16;" :: "r"(dst), "l"(src));
}

#define GBUF   49152u   // per stage: A 16K | Bh 16K | Bl 16K
#define STAGES 4

__global__ void __launch_bounds__(256) k_mgemm(
    const __half* __restrict__ Ax, const __half* __restrict__ Ah2,
    int kcx, int lda,
    const __half* __restrict__ Bh, const __half* __restrict__ Bl, int ldb,
    int K,
    float* __restrict__ outF, int ldc,
    __half* __restrict__ oF, int ldo)
{
    extern __shared__ char sm[];
    const int tid  = threadIdx.x;
    const int wid  = tid >> 5;
    const int lane = tid & 31;
    const int rowTile = blockIdx.y * 128;
    const int colTile = blockIdx.x * 128;
    const int warp_m = (wid >> 2) * 64;
    const int warp_n = (wid & 3) * 32;
    const uint32_t smb = smem_u32(sm);
    const int nch = K >> 6;

    float d[4][4][4];
#pragma unroll
    for (int a = 0; a < 4; ++a)
#pragma unroll
        for (int b = 0; b < 4; ++b)
#pragma unroll
            for (int q = 0; q < 4; ++q) d[a][b][q] = 0.f;

    auto issue = [&](int c) {
        const uint32_t dstBase = smb + (uint32_t)(c % STAGES) * GBUF;
        const int ca = (c < kcx) ? c : c - kcx;
#pragma unroll
        for (int it = 0; it < 12; ++it) {
            int i  = tid + it * 256;
            int sp = i >> 10;                 // 0 A, 1 Bh, 2 Bl
            int r  = (i & 1023) >> 3;
            int f  = i & 7;
            const void* src;
            if (sp == 0) {
                const __half* ab = (c < kcx) ? Ax : Ah2;
                src = ab + (size_t)(rowTile + r) * lda + ca * 64 + f * 8;
            } else {
                src = ((sp == 1) ? Bh : Bl) + (size_t)(colTile + r) * ldb + c * 64 + f * 8;
            }
            cp16(dstBase + sp * 16384u + SWZ((uint32_t)(r * 128 + f * 16)), src);
        }
        asm volatile("cp.async.commit_group;" ::: "memory");
    };

    issue(0);
    if (nch > 1) issue(1);
    if (nch > 2) issue(2);
    if (nch > 3) issue(3);

    for (int c = 0; c < nch; ++c) {
        int w = nch - 1 - c;
        if (w >= 3)      asm volatile("cp.async.wait_group 3;" ::: "memory");
        else if (w == 2) asm volatile("cp.async.wait_group 2;" ::: "memory");
        else if (w == 1) asm volatile("cp.async.wait_group 1;" ::: "memory");
        else             asm volatile("cp.async.wait_group 0;" ::: "memory");
        __syncthreads();

        const uint32_t sm0 = smb + (uint32_t)(c % STAGES) * GBUF;
        const int laneRowA = warp_m + (lane & 15);
        const uint32_t kbA = (uint32_t)((lane >> 4) * 16);
        const int nrowB = warp_n + (lane & 7) + ((lane >> 4) << 3);
        const uint32_t kbB = (uint32_t)(((lane >> 3) & 1) * 16);

#pragma unroll
        for (int ks = 0; ks < 4; ++ks) {
            uint32_t a[4][4], bh[4][2], bl[4][2];
#pragma unroll
            for (int mt = 0; mt < 4; ++mt) {
                uint32_t off = SWZ((uint32_t)((laneRowA + mt * 16) * 128) + ks * 32 + kbA);
                ldsm4(sm0 + off, a[mt]);
            }
#pragma unroll
            for (int np = 0; np < 2; ++np) {
                uint32_t off = SWZ((uint32_t)((nrowB + np * 16) * 128) + ks * 32 + kbB);
                uint32_t r0[4], r1[4];
                ldsm4(sm0 + 16384u + off, r0);
                ldsm4(sm0 + 32768u + off, r1);
                bh[2 * np][0] = r0[0]; bh[2 * np][1] = r0[1];
                bh[2 * np + 1][0] = r0[2]; bh[2 * np + 1][1] = r0[3];
                bl[2 * np][0] = r1[0]; bl[2 * np][1] = r1[1];
                bl[2 * np + 1][0] = r1[2]; bl[2 * np + 1][1] = r1[3];
            }
#pragma unroll
            for (int mt = 0; mt < 4; ++mt)
#pragma unroll
                for (int nt = 0; nt < 4; ++nt) {
                    mma16816(d[mt][nt], a[mt], bh[nt]);
                    mma16816(d[mt][nt], a[mt], bl[nt]);
                }
        }
        if (c + STAGES < nch) {
            __syncthreads();
            issue(c + STAGES);
        }
    }

    // --- epilogue ---
#pragma unroll
    for (int mt = 0; mt < 4; ++mt) {
        int m0 = rowTile + warp_m + mt * 16 + (lane >> 2);
#pragma unroll
        for (int nt = 0; nt < 4; ++nt) {
            int n0 = colTile + warp_n + nt * 8 + (lane & 3) * 2;
#pragma unroll
            for (int half = 0; half < 2; ++half) {
                int m = m0 + half * 8;
                float v0 = d[mt][nt][half * 2], v1 = d[mt][nt][half * 2 + 1];
                *(float2*)&outF[(size_t)m * ldc + n0] = make_float2(v0, v1);
                if (oF)
                    *(uint32_t*)&oF[(size_t)m * ldo + n0] = pack_h2(v0, v1);
            }
        }
    }
}

// ---------------------------------------------------------------------------
// Chebyshev propagation. Level 1: out = L@in (fp32 + fp16).
// Level 2: out = 2*L@in - sub (fp16 only). Warp per (t, node).
// fp32 arrays stride S32, fp16 stride NB.
// ---------------------------------------------------------------------------
__global__ void k_prop1(const float* __restrict__ in32, float* __restrict__ out32,
                        __half* __restrict__ oh, int nWarp)
{
    int gw = (blockIdx.x * blockDim.x + threadIdx.x) >> 5;
    int lane = threadIdx.x & 31;
    if (gw >= nWarp) return;
    int t = gw / NN;
    int n = gw - t * NN;
    size_t so32 = (size_t)t * MPAD * S32;
    size_t sof  = (size_t)t * MPAD * NB;

    int start = g_rowptr[n], end = g_rowptr[n + 1];
    float4 acc = make_float4(0.f, 0.f, 0.f, 0.f);
#pragma unroll 2
    for (int e = start; e < end; ++e) {
        int   s = g_col[e];
        float w = g_val[e];
        float4 v = ((const float4*)(in32 + so32 + (size_t)s * S32))[lane];
        acc.x += w * v.x; acc.y += w * v.y; acc.z += w * v.z; acc.w += w * v.w;
    }
    ((float4*)(out32 + so32 + (size_t)n * S32))[lane] = acc;
    uint2 u;
    u.x = pack_h2(acc.x, acc.y);
    u.y = pack_h2(acc.z, acc.w);
    *(uint2*)(oh + sof + (size_t)n * NB + lane * 4) = u;
}

__global__ void k_prop2k(const float* __restrict__ in32, const float* __restrict__ sub32,
                         __half* __restrict__ oh, int nWarp)
{
    int gw = (blockIdx.x * blockDim.x + threadIdx.x) >> 5;
    int lane = threadIdx.x & 31;
    if (gw >= nWarp) return;
    int t = gw / NN;
    int n = gw - t * NN;
    size_t so32 = (size_t)t * MPAD * S32;
    size_t sof  = (size_t)t * MPAD * NB;

    int start = g_rowptr[n], end = g_rowptr[n + 1];
    float4 acc = make_float4(0.f, 0.f, 0.f, 0.f);
#pragma unroll 2
    for (int e = start; e < end; ++e) {
        int   s = g_col[e];
        float w = g_val[e];
        float4 v = ((const float4*)(in32 + so32 + (size_t)s * S32))[lane];
        acc.x += w * v.x; acc.y += w * v.y; acc.z += w * v.z; acc.w += w * v.w;
    }
    float4 sv = ((const float4*)(sub32 + so32 + (size_t)n * S32))[lane];
    uint2 u;
    u.x = pack_h2(2.f * acc.x - sv.x, 2.f * acc.y - sv.y);
    u.y = pack_h2(2.f * acc.z - sv.z, 2.f * acc.w - sv.w);
    *(uint2*)(oh + sof + (size_t)n * NB + lane * 4) = u;
}

// ---------------------------------------------------------------------------
// Gate fusion: writes H (fp32 block0 of Bh32, fp16 block0 of Bhf) + output
// ---------------------------------------------------------------------------
__device__ __forceinline__ float sigmoidf(float x) { return 1.f / (1.f + expf(-x)); }

__global__ void k_gate(const float* __restrict__ pw, float* __restrict__ out, int t) {
    int i = blockIdx.x * blockDim.x + threadIdx.x;
    if (i >= NN * 128) return;
    int n = i >> 7, c = i & 127;

    const float* z = &g_Z[(size_t)n * 512];
    float zi = z[c], zf = z[128 + c], zc = z[256 + c], zo = z[384 + c];
    float cold = g_Cst[(size_t)n * 128 + c];

    float I  = sigmoidf(zi + g_bias[c]       + pw[c]       * cold);
    float F  = sigmoidf(zf + g_bias[128 + c] + pw[128 + c] * cold);
    float Tc = tanhf  (zc + g_bias[256 + c]);
    float cnew = F * cold + I * Tc;
    float O  = sigmoidf(zo + g_bias[384 + c] + pw[256 + c] * cnew);
    float h  = O * tanhf(cnew);

    g_Cst[(size_t)n * 128 + c] = cnew;
    g_Bh32[(size_t)n * S32 + c] = h;
    g_Bhf[(size_t)n * NB + c] = __float2half_rn(h);
    out[((size_t)n * TT + t) * CC + c] = h;
}

// ---------------------------------------------------------------------------
// Host launcher
// ---------------------------------------------------------------------------
extern "C" void kernel_launch(void* const* d_in, const int* in_sizes, int n_in,
                              void* d_out, int out_size)
{
    const float* X     = (const float*)d_in[0];
    const void*  edges = d_in[1];
    const float* Wpool = (const float*)d_in[2];
    const float* convW = (const float*)d_in[3];
    const float* convb = (const float*)d_in[4];
    const float* pw    = (const float*)d_in[5];
    const float* gb    = (const float*)d_in[6];
    float* out = (float*)d_out;

    float *Bx32, *Bh32, *Z;
    __half *Bxf, *Bhf, *Xf, *WTh, *WTl, *Wph, *Wpl;
    cudaGetSymbolAddress((void**)&Bx32, g_Bx32);
    cudaGetSymbolAddress((void**)&Bh32, g_Bh32);
    cudaGetSymbolAddress((void**)&Z,    g_Z);
    cudaGetSymbolAddress((void**)&Bxf,  g_Bxf);
    cudaGetSymbolAddress((void**)&Bhf,  g_Bhf);
    cudaGetSymbolAddress((void**)&Xf,   g_Xf);
    cudaGetSymbolAddress((void**)&WTh,  g_WTh);
    cudaGetSymbolAddress((void**)&WTl,  g_WTl);
    cudaGetSymbolAddress((void**)&Wph,  g_Wph);
    cudaGetSymbolAddress((void**)&Wpl,  g_Wpl);

    cudaFuncSetAttribute(k_mgemm, cudaFuncAttributeMaxDynamicSharedMemorySize, STAGES * GBUF);

    const size_t SLF = (size_t)MPAD * NB;    // fp16 t-slice stride
    const size_t SL3 = (size_t)MPAD * S32;   // fp32 t-slice stride

    // 1-4: preprocessing
    k_init<<<8192, 256>>>(edges);
    k_convcount<<<(2 * EE + 255) / 256, 256>>>(edges);
    k_scan_dinv<<<50, 1024>>>();
    k_fps<<<FPS_FILL_BLK + FPS_PREP_BLK + FPS_SPLIT_BLK, 256>>>(X, convW, convb, gb, Wpool);

    // 5: pool GEMM, all timesteps: Xp = X @ Wpool^T -> Bx32 blk0 (fp32) + Bxf blk0 (fp16)
    k_mgemm<<<dim3(1, TT * MPAD / 128), 256, STAGES * GBUF>>>(
        Xf, Xf, 99, 128, Wph, Wpl, 128, 128,
        Bx32, S32, Bxf, NB);

    // 6-7: x-path Chebyshev basis, all timesteps batched
    k_prop1<<<TT * NN / 4, 128>>>(Bx32, Bx32 + 128, Bxf + 128, TT * NN);
    k_prop2k<<<TT * NN / 4, 128>>>(Bx32 + 128, Bx32, Bxf + 256, TT * NN);

    // recurrent loop
    for (int t = 0; t < TT; ++t) {
        if (t > 0) {
            k_prop1<<<NN / 4, 128>>>(Bh32, Bh32 + 128, Bhf + 128, NN);
            k_prop2k<<<NN / 4, 128>>>(Bh32 + 128, Bh32, Bhf + 256, NN);
        }
        // Z = [x-basis_t | h-basis] (N x 768) @ W_all^T (768 x 512)
        k_mgemm<<<dim3(4, MPAD / 128), 256, STAGES * GBUF>>>(
            Bxf + (size_t)t * SLF, Bhf, 6, NB,
            WTh, WTl, 768, 768, Z, 512, nullptr, 0);
        k_gate<<<(NN * 128 + 255) / 256, 256>>>(pw, out, t);
    }
}